// round 3
// baseline (speedup 1.0000x reference)
#include <cuda_runtime.h>

#define NC       80
#define AN       3
#define C_IN     258      // 3 + 3*85
#define T_TOTAL  22743    // 3*(361+1444+5776)
#define TS       32       // spatial positions per block tile
#define PAD      33       // smem row pitch (bank-conflict free)

__constant__ float ANCH[3][3][2] = {
    {{116.f, 90.f}, {156.f, 198.f}, {373.f, 326.f}},
    {{ 30.f, 61.f}, { 62.f,  45.f}, { 59.f, 119.f}},
    {{ 10.f, 13.f}, { 16.f,  30.f}, { 33.f,  23.f}}
};

__device__ __forceinline__ float sigm(float x) {
    return __fdividef(1.f, 1.f + __expf(-x));
}

__global__ __launch_bounds__(256)
void yolo_decode_kernel(const float* __restrict__ in,
                        const float* __restrict__ im_size,
                        float* __restrict__ boxes,
                        float* __restrict__ scores,
                        int H, int W, float stride, int lvl, int lvl_off)
{
    __shared__ float sm[C_IN * PAD];
    __shared__ float confsm[AN * TS];

    const int S   = H * W;
    const int b   = blockIdx.y;
    const int s0  = blockIdx.x * TS;
    const int tid = threadIdx.x;

    const float* __restrict__ inb = in + (size_t)b * C_IN * S;

    // ---- Phase A: coalesced stage of 258 channels x 32 spatial into smem ----
    #pragma unroll 4
    for (int i = tid; i < C_IN * TS; i += 256) {
        int c  = i >> 5;
        int sp = i & 31;
        int s  = s0 + sp;
        sm[c * PAD + sp] = (s < S) ? __ldg(inb + (size_t)c * S + s) : 0.f;
    }
    __syncthreads();

    const float imh = __ldg(im_size + b * 2 + 0);
    const float imw = __ldg(im_size + b * 2 + 1);
    const float inv_hs = __fdividef(1.f, (float)H * stride);
    const float sclx = imw * inv_hs;
    const float scly = imh * inv_hs;

    // ---- Phase B: conf + boxes, one thread per (sp, anchor) ----
    if (tid < AN * TS) {
        int sp = tid / 3;            // thread order matches box output order
        int a  = tid - sp * 3;
        int s  = s0 + sp;
        if (s < S) {
            const int cb = 3 + a * 85;
            float ip = sigm(sm[a * PAD + sp]);
            float dx = sm[(cb + 0) * PAD + sp];
            float dy = sm[(cb + 1) * PAD + sp];
            float dw = sm[(cb + 2) * PAD + sp];
            float dh = sm[(cb + 3) * PAD + sp];
            float to = sm[(cb + 4) * PAD + sp];

            float obj  = sigm(to);
            float nobj = __expf(0.6f * __logf(obj) + 0.4f * __logf(ip));
            // conf = sigmoid(de_sigmoid(nobj)) = 1/(1 + clamp(1/clamp(nobj)-1))
            float n = fminf(fmaxf(nobj, 1e-7f), 1e7f);
            float y = __fdividef(1.f, n) - 1.f;
            y = fminf(fmaxf(y, 1e-7f), 1e7f);
            float conf = __fdividef(1.f, 1.f + y);
            confsm[a * TS + sp] = conf;

            float gx = (float)(s % W);
            float gy = (float)(s / W);
            float cx = (1.05f * sigm(dx) + gx - 0.025f) * stride;
            float cy = (1.05f * sigm(dy) + gy - 0.025f) * stride;
            float ww = __expf(dw) * ANCH[lvl][a][0];
            float hh = __expf(dh) * ANCH[lvl][a][1];

            float x0 = (cx - 0.5f * ww) * sclx;
            float y0 = (cy - 0.5f * hh) * scly;
            float x1 = (cx + 0.5f * ww) * sclx;
            float y1 = (cy + 0.5f * hh) * scly;
            x0 = x0 < 0.f  ? 0.f : x0;
            y0 = y0 < 0.f  ? 0.f : y0;
            x1 = x1 > imw  ? imw : x1;
            y1 = y1 > imh  ? imh : y1;

            float4 bx = make_float4(x0, y0, x1, y1);
            ((float4*)boxes)[(size_t)b * T_TOTAL + lvl_off + s0 * 3 + tid] = bx;
        }
    }
    __syncthreads();

    // ---- Phase C: scores, output-linear sweep (coalesced writes) ----
    // Score region of this tile is contiguous in the output:
    //   sbase + sp*(AN*NC) + a*NC + cls  ==  sbase + i
    // Strength-reduced decomposition with PROPER carry:
    //   i += 256  <=>  sp += 1, r += 16, carry when r >= 240.
    const size_t sbase = ((size_t)b * T_TOTAL + lvl_off + (size_t)s0 * 3) * NC;
    {
        int i  = tid;
        int sp = i / (AN * NC);          // 0 or 1 for tid < 256
        int r  = i - sp * (AN * NC);
        #pragma unroll 1
        while (i < TS * AN * NC) {
            int a   = (r >= 2 * NC) ? 2 : (r >= NC ? 1 : 0);
            int cls = r - a * NC;
            int s   = s0 + sp;
            if (s < S) {
                float p = sm[(3 + a * 85 + 5 + cls) * PAD + sp];
                scores[sbase + i] = confsm[a * TS + sp] * sigm(p);
            }
            i  += 256;
            sp += 1;
            r  += 256 - AN * NC;         // +16
            if (r >= AN * NC) { r -= AN * NC; sp += 1; }
        }
    }
}

extern "C" void kernel_launch(void* const* d_in, const int* in_sizes, int n_in,
                              void* d_out, int out_size)
{
    const float* out0 = (const float*)d_in[0];   // [B,258,19,19]
    const float* out1 = (const float*)d_in[1];   // [B,258,38,38]
    const float* out2 = (const float*)d_in[2];   // [B,258,76,76]
    const float* imsz = (const float*)d_in[3];   // [B,2]
    const int B = in_sizes[3] / 2;

    float* boxes  = (float*)d_out;
    float* scores = boxes + (size_t)B * T_TOTAL * 4;

    // level 0: 19x19, stride 32, anchor offset 0
    {
        dim3 grid((361 + TS - 1) / TS, B);
        yolo_decode_kernel<<<grid, 256>>>(out0, imsz, boxes, scores,
                                          19, 19, 32.f, 0, 0);
    }
    // level 1: 38x38, stride 16, anchor offset 1083
    {
        dim3 grid((1444 + TS - 1) / TS, B);
        yolo_decode_kernel<<<grid, 256>>>(out1, imsz, boxes, scores,
                                          38, 38, 16.f, 1, 1083);
    }
    // level 2: 76x76, stride 8, anchor offset 5415
    {
        dim3 grid((5776 + TS - 1) / TS, B);
        yolo_decode_kernel<<<grid, 256>>>(out2, imsz, boxes, scores,
                                          76, 76, 8.f, 2, 5415);
    }
}

// round 5
// speedup vs baseline: 1.3523x; 1.3523x over previous
#include <cuda_runtime.h>

#define NC       80
#define AN       3
#define C_IN     258      // 3 + 3*85
#define T_TOTAL  22743    // 3*(361+1444+5776)
#define TS       32       // spatial positions per block tile
#define PAD      33       // smem row pitch (bank-conflict free)
#define NTILES   239      // 12 + 46 + 181

__constant__ float ANCH[3][3][2] = {
    {{116.f, 90.f}, {156.f, 198.f}, {373.f, 326.f}},
    {{ 30.f, 61.f}, { 62.f,  45.f}, { 59.f, 119.f}},
    {{ 10.f, 13.f}, { 16.f,  30.f}, { 33.f,  23.f}}
};

// per-level tables: H(=W), S, stride, first tile, lvl_off (anchor rows before level)
__constant__ int   LV_H[3]      = {19, 38, 76};
__constant__ int   LV_S[3]      = {361, 1444, 5776};
__constant__ float LV_STRIDE[3] = {32.f, 16.f, 8.f};
__constant__ int   LV_T0[3]     = {0, 12, 58};
__constant__ int   LV_OFF[3]    = {0, 1083, 5415};

__device__ __forceinline__ float sigm(float x) {
    return __fdividef(1.f, 1.f + __expf(-x));
}

__global__ __launch_bounds__(256)
void yolo_decode_fused(const float* __restrict__ in0,
                       const float* __restrict__ in1,
                       const float* __restrict__ in2,
                       const float* __restrict__ im_size,
                       float* __restrict__ boxes,
                       float* __restrict__ scores)
{
    __shared__ float sm[C_IN * PAD];
    __shared__ float confsm[AN * TS];

    const int bx  = blockIdx.x;          // global tile id in [0, 239)
    const int b   = blockIdx.y;          // batch
    const int tid = threadIdx.x;

    // resolve level
    int lvl = (bx >= 12) + (bx >= 58);
    const int   H      = LV_H[lvl];
    const int   S      = LV_S[lvl];
    const float stride = LV_STRIDE[lvl];
    const int   s0     = (bx - LV_T0[lvl]) * TS;
    const int   lvl_off= LV_OFF[lvl];
    const float* __restrict__ in = (lvl == 0) ? in0 : (lvl == 1) ? in1 : in2;

    const float* __restrict__ inb = in + (size_t)b * C_IN * S;
    const bool full = (s0 + TS <= S);

    // ---- Phase A: coalesced stage of 258 channels x 32 spatial into smem ----
    if (full) {
        #pragma unroll 8
        for (int i = tid; i < C_IN * TS; i += 256) {
            int c  = i >> 5;
            int sp = i & 31;
            sm[c * PAD + sp] = __ldg(inb + (size_t)c * S + s0 + sp);
        }
    } else {
        #pragma unroll 4
        for (int i = tid; i < C_IN * TS; i += 256) {
            int c  = i >> 5;
            int sp = i & 31;
            int s  = s0 + sp;
            sm[c * PAD + sp] = (s < S) ? __ldg(inb + (size_t)c * S + s) : 0.f;
        }
    }
    __syncthreads();

    const float imh = __ldg(im_size + b * 2 + 0);
    const float imw = __ldg(im_size + b * 2 + 1);
    const float inv_hs = __fdividef(1.f, (float)H * stride);
    const float sclx = imw * inv_hs;
    const float scly = imh * inv_hs;

    // ---- Phase B: conf + boxes, one thread per (sp, anchor) ----
    if (tid < AN * TS) {
        int sp = tid / 3;            // thread order matches box output order
        int a  = tid - sp * 3;
        int s  = s0 + sp;
        if (s < S) {
            const int cb = 3 + a * 85;
            float ip = sigm(sm[a * PAD + sp]);
            float dx = sm[(cb + 0) * PAD + sp];
            float dy = sm[(cb + 1) * PAD + sp];
            float dw = sm[(cb + 2) * PAD + sp];
            float dh = sm[(cb + 3) * PAD + sp];
            float to = sm[(cb + 4) * PAD + sp];

            float obj  = sigm(to);
            float nobj = __expf(0.6f * __logf(obj) + 0.4f * __logf(ip));
            // conf = sigmoid(de_sigmoid(nobj)) = 1/(1 + clamp(1/clamp(nobj)-1))
            float n = fminf(fmaxf(nobj, 1e-7f), 1e7f);
            float y = __fdividef(1.f, n) - 1.f;
            y = fminf(fmaxf(y, 1e-7f), 1e7f);
            float conf = __fdividef(1.f, 1.f + y);
            confsm[a * TS + sp] = conf;

            float gx = (float)(s % H);   // W == H for all levels
            float gy = (float)(s / H);
            float cx = (1.05f * sigm(dx) + gx - 0.025f) * stride;
            float cy = (1.05f * sigm(dy) + gy - 0.025f) * stride;
            float ww = __expf(dw) * ANCH[lvl][a][0];
            float hh = __expf(dh) * ANCH[lvl][a][1];

            float x0 = (cx - 0.5f * ww) * sclx;
            float y0 = (cy - 0.5f * hh) * scly;
            float x1 = (cx + 0.5f * ww) * sclx;
            float y1 = (cy + 0.5f * hh) * scly;
            x0 = x0 < 0.f  ? 0.f : x0;
            y0 = y0 < 0.f  ? 0.f : y0;
            x1 = x1 > imw  ? imw : x1;
            y1 = y1 > imh  ? imh : y1;

            float4 bxv = make_float4(x0, y0, x1, y1);
            __stcs(((float4*)boxes) + (size_t)b * T_TOTAL + lvl_off + s0 * 3 + tid, bxv);
        }
    }
    __syncthreads();

    // ---- Phase C: scores, output-linear sweep (coalesced writes) ----
    const size_t sbase = ((size_t)b * T_TOTAL + lvl_off + (size_t)s0 * 3) * NC;
    if (full) {
        // float4 path: tile = 1920 float4s, each inside one (sp, anchor) row.
        //   j -> sp = j/60, rem = j%60, a = rem/20, c4 = rem%20
        float4* __restrict__ out4 = (float4*)(scores + sbase);
        #pragma unroll 1
        for (int j = tid; j < TS * AN * NC / 4; j += 256) {
            int sp  = j / 60;
            int rem = j - sp * 60;
            int a   = rem / 20;
            int c4  = rem - a * 20;
            int ch  = 8 + a * 85 + c4 * 4;      // prob channel base
            float conf = confsm[a * TS + sp];
            float4 v;
            v.x = conf * sigm(sm[(ch + 0) * PAD + sp]);
            v.y = conf * sigm(sm[(ch + 1) * PAD + sp]);
            v.z = conf * sigm(sm[(ch + 2) * PAD + sp]);
            v.w = conf * sigm(sm[(ch + 3) * PAD + sp]);
            __stcs(out4 + j, v);
        }
    } else {
        #pragma unroll 1
        for (int i = tid; i < TS * AN * NC; i += 256) {
            int sp  = i / (AN * NC);
            int r   = i - sp * (AN * NC);
            int a   = r / NC;
            int cls = r - a * NC;
            int s   = s0 + sp;
            if (s < S) {
                float p = sm[(8 + a * 85 + cls) * PAD + sp];
                __stcs(scores + sbase + i, confsm[a * TS + sp] * sigm(p));
            }
        }
    }
}

extern "C" void kernel_launch(void* const* d_in, const int* in_sizes, int n_in,
                              void* d_out, int out_size)
{
    const float* out0 = (const float*)d_in[0];   // [B,258,19,19]
    const float* out1 = (const float*)d_in[1];   // [B,258,38,38]
    const float* out2 = (const float*)d_in[2];   // [B,258,76,76]
    const float* imsz = (const float*)d_in[3];   // [B,2]
    const int B = in_sizes[3] / 2;

    float* boxes  = (float*)d_out;
    float* scores = boxes + (size_t)B * T_TOTAL * 4;

    dim3 grid(NTILES, B);
    yolo_decode_fused<<<grid, 256>>>(out0, out1, out2, imsz, boxes, scores);
}

// round 7
// speedup vs baseline: 1.5710x; 1.1617x over previous
#include <cuda_runtime.h>

#define NC       80
#define AN       3
#define C_IN     258      // 3 + 3*85
#define T_TOTAL  22743    // 3*(361+1444+5776)
#define TS       32       // spatial positions per block tile
#define PITCH    260      // floats per sp-row (mod 4 == 0 for LDS.128)
#define PITCH4   65       // float4 units per sp-row
#define NTILES   239      // 12 + 46 + 181
#define NTHREADS 512

__constant__ float ANCH[3][3][2] = {
    {{116.f, 90.f}, {156.f, 198.f}, {373.f, 326.f}},
    {{ 30.f, 61.f}, { 62.f,  45.f}, { 59.f, 119.f}},
    {{ 10.f, 13.f}, { 16.f,  30.f}, { 33.f,  23.f}}
};

__constant__ int   LV_H[3]      = {19, 38, 76};
__constant__ int   LV_S[3]      = {361, 1444, 5776};
__constant__ float LV_STRIDE[3] = {32.f, 16.f, 8.f};
__constant__ int   LV_T0[3]     = {0, 12, 58};
__constant__ int   LV_OFF[3]    = {0, 1083, 5415};

__device__ __forceinline__ float sigm(float x) {
    return __fdividef(1.f, 1.f + __expf(-x));
}

// channel -> smem slot remap:
//   probs  (c = 8+85a .. 87+85a)  -> a*80 + (c-8-85a)   [slots 0..239]
//   box/obj(c = 3+85a .. 7+85a)   -> 240 + a*5 + t      [slots 240..254]
//   ioup   (c = 0..2)             -> 255 + c            [slots 255..257]
__device__ __forceinline__ int chan_slot(int c) {
    if (c < 3) return 255 + c;
    int d = c - 3;
    int a = d / 85;           // magic-mul, warp-uniform in Phase A
    int r = d - a * 85;
    return (r < 5) ? (240 + a * 5 + r) : (a * 80 + r - 5);
}

__global__ __launch_bounds__(NTHREADS, 4)
void yolo_decode_fused(const float* __restrict__ in0,
                       const float* __restrict__ in1,
                       const float* __restrict__ in2,
                       const float* __restrict__ im_size,
                       float* __restrict__ boxes,
                       float* __restrict__ scores)
{
    __shared__ __align__(16) float sm[TS * PITCH];   // 33.28 KB, transposed [sp][slot]
    __shared__ float confsm[AN * TS];

    const int bx  = blockIdx.x;          // tile id in [0, 239)
    const int b   = blockIdx.y;          // batch
    const int tid = threadIdx.x;

    int lvl = (bx >= 12) + (bx >= 58);
    const int   H      = LV_H[lvl];
    const int   S      = LV_S[lvl];
    const float stride = LV_STRIDE[lvl];
    const int   s0     = (bx - LV_T0[lvl]) * TS;
    const int   lvl_off= LV_OFF[lvl];
    const float* __restrict__ in = (lvl == 0) ? in0 : (lvl == 1) ? in1 : in2;

    const float* __restrict__ inb = in + (size_t)b * C_IN * S;
    const bool full = (s0 + TS <= S);

    // ---- Phase A: coalesced gmem read (c-major), transposed smem write ----
    if (full) {
        #pragma unroll 4
        for (int i = tid; i < C_IN * TS; i += NTHREADS) {
            int c    = i >> 5;
            int sp   = i & 31;
            int slot = chan_slot(c);
            sm[sp * PITCH + slot] = __ldg(inb + c * S + s0 + sp);
        }
    } else {
        #pragma unroll 4
        for (int i = tid; i < C_IN * TS; i += NTHREADS) {
            int c    = i >> 5;
            int sp   = i & 31;
            int slot = chan_slot(c);
            int s    = s0 + sp;
            sm[sp * PITCH + slot] = (s < S) ? __ldg(inb + c * S + s) : 0.f;
        }
    }
    __syncthreads();

    const float imh = __ldg(im_size + b * 2 + 0);
    const float imw = __ldg(im_size + b * 2 + 1);
    const float inv_hs = __fdividef(1.f, (float)H * stride);
    const float sclx = imw * inv_hs;
    const float scly = imh * inv_hs;

    // ---- Phase B: conf + boxes, one thread per (sp, anchor) ----
    if (tid < AN * TS) {
        int sp = tid / 3;                // thread order == box output order
        int a  = tid - sp * 3;
        int s  = s0 + sp;
        if (s < S) {
            const float* row = sm + sp * PITCH;
            float ip = sigm(row[255 + a]);
            const int bb = 240 + a * 5;
            float dx = row[bb + 0];
            float dy = row[bb + 1];
            float dw = row[bb + 2];
            float dh = row[bb + 3];
            float to = row[bb + 4];

            float obj  = sigm(to);
            float nobj = __expf(0.6f * __logf(obj) + 0.4f * __logf(ip));
            // conf = sigmoid(de_sigmoid(nobj)) = 1/(1 + clamp(1/clamp(nobj)-1))
            float n = fminf(fmaxf(nobj, 1e-7f), 1e7f);
            float y = __fdividef(1.f, n) - 1.f;
            y = fminf(fmaxf(y, 1e-7f), 1e7f);
            float conf = __fdividef(1.f, 1.f + y);
            confsm[a * TS + sp] = conf;

            float gx = (float)(s % H);   // W == H for all levels
            float gy = (float)(s / H);
            float cx = (1.05f * sigm(dx) + gx - 0.025f) * stride;
            float cy = (1.05f * sigm(dy) + gy - 0.025f) * stride;
            float ww = __expf(dw) * ANCH[lvl][a][0];
            float hh = __expf(dh) * ANCH[lvl][a][1];

            float x0 = (cx - 0.5f * ww) * sclx;
            float y0 = (cy - 0.5f * hh) * scly;
            float x1 = (cx + 0.5f * ww) * sclx;
            float y1 = (cy + 0.5f * hh) * scly;
            x0 = x0 < 0.f  ? 0.f : x0;
            y0 = y0 < 0.f  ? 0.f : y0;
            x1 = x1 > imw  ? imw : x1;
            y1 = y1 > imh  ? imh : y1;

            float4 bxv = make_float4(x0, y0, x1, y1);
            __stcs(((float4*)boxes) + (size_t)b * T_TOTAL + lvl_off + s0 * 3 + tid, bxv);
        }
    }
    __syncthreads();

    // ---- Phase C: scores. LDS.128 from transposed smem, STG.128 streaming ----
    //   j in [0,1920): sp = j/60, rem = j%60 (== float4 unit within row),
    //   a = rem/20. smem read: sm4[sp*65 + rem]  (16B aligned, conflict-free)
    const size_t sbase = ((size_t)b * T_TOTAL + lvl_off + (size_t)s0 * 3) * NC;
    if (full) {
        const float4* __restrict__ sm4  = (const float4*)sm;
        float4* __restrict__       out4 = (float4*)(scores + sbase);
        #pragma unroll 2
        for (int j = tid; j < TS * AN * NC / 4; j += NTHREADS) {
            int sp  = j / 60;
            int rem = j - sp * 60;
            int a   = rem / 20;
            float conf = confsm[a * TS + sp];
            float4 p = sm4[sp * PITCH4 + rem];
            float4 v;
            v.x = conf * sigm(p.x);
            v.y = conf * sigm(p.y);
            v.z = conf * sigm(p.z);
            v.w = conf * sigm(p.w);
            __stcs(out4 + j, v);
        }
    } else {
        #pragma unroll 1
        for (int i = tid; i < TS * AN * NC; i += NTHREADS) {
            int sp  = i / (AN * NC);
            int r   = i - sp * (AN * NC);
            int a   = r / NC;
            int cls = r - a * NC;
            int s   = s0 + sp;
            if (s < S) {
                float p = sm[sp * PITCH + a * 80 + cls];
                __stcs(scores + sbase + i, confsm[a * TS + sp] * sigm(p));
            }
        }
    }
}

extern "C" void kernel_launch(void* const* d_in, const int* in_sizes, int n_in,
                              void* d_out, int out_size)
{
    const float* out0 = (const float*)d_in[0];   // [B,258,19,19]
    const float* out1 = (const float*)d_in[1];   // [B,258,38,38]
    const float* out2 = (const float*)d_in[2];   // [B,258,76,76]
    const float* imsz = (const float*)d_in[3];   // [B,2]
    const int B = in_sizes[3] / 2;

    float* boxes  = (float*)d_out;
    float* scores = boxes + (size_t)B * T_TOTAL * 4;

    dim3 grid(NTILES, B);
    yolo_decode_fused<<<grid, NTHREADS>>>(out0, out1, out2, imsz, boxes, scores);
}